// round 1
// baseline (speedup 1.0000x reference)
#include <cuda_runtime.h>

// Problem constants (fixed by the dataset shapes)
#define HWC   65536      // 256*256
#define BATCH 64
#define NATT  4096
#define MREP  2048

// Global accumulators: [0]=S_attract, [1]=N_attract, [2]=S_repel, [3]=N_repel
__device__ double g_acc[4];

__global__ void init_acc_kernel() {
    if (threadIdx.x < 4) g_acc[threadIdx.x] = 0.0;
}

__device__ __forceinline__ float iou_f(float hA, float yA, float xA,
                                       float hB, float yB, float xB) {
    float areaA = hA * hA * 0.41f;
    float areaB = hB * hB * 0.41f;
    float y_min_max = fmaxf(yA - hA * 0.5f,        yB - hB * 0.5f);
    float x_min_max = fmaxf(xA - 0.41f * hA * 0.5f, xB - 0.41f * hB * 0.5f);
    float y_max_min = fminf(yA + hA * 0.5f,        yB + hB * 0.5f);
    float x_max_min = fminf(xA + 0.41f * hA * 0.5f, xB + 0.41f * hB * 0.5f);
    float I = fmaxf(y_max_min - y_min_max, 0.0f) * fmaxf(x_max_min - x_min_max, 0.0f);
    float U = areaA + areaB - I;
    return I / (U + 1e-6f);
}

// Block-wide reduction of (v0, v1), then double atomics into acc0/acc1.
// Assumes blockDim.x == 256.
__device__ __forceinline__ void block_reduce2(float v0, float v1,
                                              double* acc0, double* acc1) {
    #pragma unroll
    for (int o = 16; o > 0; o >>= 1) {
        v0 += __shfl_down_sync(0xFFFFFFFFu, v0, o);
        v1 += __shfl_down_sync(0xFFFFFFFFu, v1, o);
    }
    __shared__ float s0[8], s1[8];
    int lane = threadIdx.x & 31;
    int warp = threadIdx.x >> 5;
    if (lane == 0) { s0[warp] = v0; s1[warp] = v1; }
    __syncthreads();
    if (warp == 0) {
        v0 = (lane < 8) ? s0[lane] : 0.0f;
        v1 = (lane < 8) ? s1[lane] : 0.0f;
        #pragma unroll
        for (int o = 4; o > 0; o >>= 1) {
            v0 += __shfl_down_sync(0x000000FFu, v0, o);
            v1 += __shfl_down_sync(0x000000FFu, v1, o);
        }
        if (lane == 0) {
            atomicAdd(acc0, (double)v0);
            atomicAdd(acc1, (double)v1);
        }
    }
}

// One thread per (b, n). Grid = B*N/256 = 1024 blocks.
__global__ __launch_bounds__(256)
void attract_kernel(const float* __restrict__ oh,
                    const float* __restrict__ ooff,
                    const int*   __restrict__ attract,
                    const unsigned char* __restrict__ mask) {
    int gid = blockIdx.x * 256 + threadIdx.x;   // b*NATT + n
    int b   = gid >> 12;                        // / 4096

    int4 idx4 = reinterpret_cast<const int4*>(attract)[gid];
    unsigned int m4 = reinterpret_cast<const unsigned int*>(mask)[gid];

    const float* ohb = oh   + (size_t)b * HWC;
    const float* o0b = ooff + (size_t)b * 2 * HWC;
    const float* o1b = o0b + HWC;

    int ind[4] = {idx4.x, idx4.y, idx4.z, idx4.w};
    float h[4], o0[4], o1[4];
    #pragma unroll
    for (int k = 0; k < 4; k++) {
        h[k]  = __ldg(ohb + ind[k]);
        o0[k] = __ldg(o0b + ind[k]);
        o1[k] = __ldg(o1b + ind[k]);
    }

    // Corner offsets: OFFSETS = [[0,0],[1,0],[0,1],[1,1]] added to (o0,o1)
    const float kx[4] = {0.f, 1.f, 0.f, 1.f};
    const float ky[4] = {0.f, 0.f, 1.f, 1.f};

    float hm = 0.f, o0m = 0.f, o1m = 0.f;
    #pragma unroll
    for (int k = 0; k < 4; k++) {
        o0[k] += kx[k];
        o1[k] += ky[k];
        hm  += h[k];
        o0m += o0[k];
        o1m += o1[k];
    }
    hm *= 0.25f; o0m *= 0.25f; o1m *= 0.25f;
    float hB = expf(hm);

    float lsum = 0.f, cnt = 0.f;
    #pragma unroll
    for (int k = 0; k < 4; k++) {
        if ((m4 >> (8 * k)) & 0xFFu) {
            lsum += 1.0f - iou_f(expf(h[k]), o0[k], o1[k], hB, o0m, o1m);
            cnt  += 1.0f;
        }
    }
    block_reduce2(lsum, cnt, &g_acc[0], &g_acc[1]);
}

// One thread per (b, m). Grid = B*M/256 = 512 blocks.
__global__ __launch_bounds__(256)
void repel_kernel(const float* __restrict__ oh,
                  const float* __restrict__ ooff,
                  const float* __restrict__ pre_off,
                  const int*   __restrict__ repel,
                  const unsigned char* __restrict__ mask) {
    int gid = blockIdx.x * 256 + threadIdx.x;   // b*MREP + m
    int b   = gid >> 11;                        // / 2048

    const int4* rp = reinterpret_cast<const int4*>(repel) + (size_t)gid * 2;
    int4 i0 = rp[0];   // box 0 corners
    int4 i1 = rp[1];   // box 1 corners

    const float* ohb = oh   + (size_t)b * HWC;
    const float* o0b = ooff + (size_t)b * 2 * HWC;
    const float* o1b = o0b + HWC;

    int ind[8] = {i0.x, i0.y, i0.z, i0.w, i1.x, i1.y, i1.z, i1.w};
    float hs[8], a0[8], a1[8];
    #pragma unroll
    for (int k = 0; k < 8; k++) {
        hs[k] = __ldg(ohb + ind[k]);
        a0[k] = __ldg(o0b + ind[k]);
        a1[k] = __ldg(o1b + ind[k]);
    }

    float hmean[2], y[2], x[2];
    #pragma unroll
    for (int j = 0; j < 2; j++) {
        float hsum = 0.f, s0 = 0.f, s1 = 0.f;
        #pragma unroll
        for (int k = 0; k < 4; k++) {
            hsum += hs[j * 4 + k];
            s0   += a0[j * 4 + k];
            s1   += a1[j * 4 + k];
        }
        hmean[j] = hsum * 0.25f;
        // mean of (off + OFFSETS): OFFSETS contributes +0.5 to each channel
        y[j] = s0 * 0.25f + 0.5f;
        x[j] = s1 * 0.25f + 0.5f;
    }
    // box 1 mean offset gets pre_off added
    float2 po = reinterpret_cast<const float2*>(pre_off)[gid];
    y[1] += po.x;
    x[1] += po.y;

    float v = iou_f(expf(hmean[0]), y[0], x[0], expf(hmean[1]), y[1], x[1]);

    float lsum = 0.f, cnt = 0.f;
    if (mask[gid]) { lsum = v; cnt = 1.0f; }
    block_reduce2(lsum, cnt, &g_acc[2], &g_acc[3]);
}

__global__ void finalize_kernel(float* out) {
    if (threadIdx.x == 0) {
        double r = g_acc[0] / (g_acc[1] + 1e-4) + g_acc[2] / (g_acc[3] + 1e-4);
        out[0] = (float)r;
    }
}

extern "C" void kernel_launch(void* const* d_in, const int* in_sizes, int n_in,
                              void* d_out, int out_size) {
    const float* output_h    = (const float*)d_in[0];  // [64,1,256,256]
    const float* output_off  = (const float*)d_in[1];  // [64,2,256,256]
    // d_in[2], d_in[3]: target_h / target_off — unused by the reference
    const float* pre_off     = (const float*)d_in[4];  // [64,2048,2]
    const int*   attract     = (const int*)  d_in[5];  // [64,4096,4]
    const int*   repel       = (const int*)  d_in[6];  // [64,2048,2,4]
    const unsigned char* mask_attract = (const unsigned char*)d_in[7];  // [64,4096,4] bool
    const unsigned char* mask_repel   = (const unsigned char*)d_in[8];  // [64,2048,1] bool
    float* out = (float*)d_out;

    init_acc_kernel<<<1, 32>>>();
    attract_kernel<<<(BATCH * NATT) / 256, 256>>>(output_h, output_off, attract, mask_attract);
    repel_kernel<<<(BATCH * MREP) / 256, 256>>>(output_h, output_off, pre_off, repel, mask_repel);
    finalize_kernel<<<1, 32>>>(out);
}